// round 2
// baseline (speedup 1.0000x reference)
#include <cuda_runtime.h>
#include <cuda_bf16.h>

#define GS_FX 500.0f

__device__ __forceinline__ float clipf(float v, float lo, float hi) {
    return fminf(fmaxf(v, lo), hi);
}

// ---------------------------------------------------------------------------
// Kernel A: geometry. 4 gaussians/thread.
// reads:  positions (3 f4), scales (3 f4)          -> 96B/thread
// writes: proj (3 f4), cov2d (4 f4), valid (1 f4)  -> 128B/thread
// ---------------------------------------------------------------------------
__global__ void __launch_bounds__(256)
gs_geo_kernel(const float4* __restrict__ pos4,
              const float4* __restrict__ sc4,
              const float*  __restrict__ vm,
              const int*    __restrict__ wp,
              const int*    __restrict__ hp,
              float4* __restrict__ out4, int G)
{
    int g = blockIdx.x * blockDim.x + threadIdx.x;
    if (g >= G) return;

    // front-batch all loads (streaming hint: no reuse)
    float4 p0 = __ldcs(&pos4[3 * g]);
    float4 p1 = __ldcs(&pos4[3 * g + 1]);
    float4 p2 = __ldcs(&pos4[3 * g + 2]);
    float4 s0 = __ldcs(&sc4[3 * g]);
    float4 s1 = __ldcs(&sc4[3 * g + 1]);
    float4 s2 = __ldcs(&sc4[3 * g + 2]);

    float r00 = vm[0], r01 = vm[1],  r02 = vm[2],  tx = vm[3];
    float r10 = vm[4], r11 = vm[5],  r12 = vm[6],  ty = vm[7];
    float r20 = vm[8], r21 = vm[9],  r22 = vm[10], tz = vm[11];
    float W = (float)(*wp), H = (float)(*hp);
    float hw = W * 0.5f, hh = H * 0.5f;
    float xmax = W + 1000.0f, ymax = H + 1000.0f;

    float px[4] = {p0.x, p0.w, p1.z, p2.y};
    float py[4] = {p0.y, p1.x, p1.w, p2.z};
    float pz[4] = {p0.z, p1.y, p2.x, p2.w};
    float sx[4] = {s0.x, s0.w, s1.z, s2.y};
    float sy[4] = {s0.y, s1.x, s1.w, s2.z};

    float xs[4], ys[4], zs[4], c00[4], c11[4], vf[4];
#pragma unroll
    for (int j = 0; j < 4; j++) {
        float ax = px[j] - tx, ay = py[j] - ty, az = pz[j] - tz;
        float vx = clipf(fmaf(r00, ax, fmaf(r01, ay, r02 * az)), -100.0f, 100.0f);
        float vy = clipf(fmaf(r10, ax, fmaf(r11, ay, r12 * az)), -100.0f, 100.0f);
        float vz = clipf(fmaf(r20, ax, fmaf(r21, ay, r22 * az)), -100.0f, 100.0f);

        vf[j] = (vz > 0.1f && vz < 10.0f) ? 1.0f : 0.0f;

        float z   = clipf(vz, 0.1f, 10.0f);
        float inv = __fdividef(GS_FX, z);   // FX == FY

        xs[j] = clipf(fmaf(vx, inv, hw), -1000.0f, xmax);
        ys[j] = clipf(fmaf(-vy, inv, hh), -1000.0f, ymax);
        zs[j] = vz;

        float ssx = fmaxf(sx[j], 0.001f) * inv;
        float ssy = fmaxf(sy[j], 0.001f) * inv;
        c00[j] = clipf(fmaf(ssx, ssx, 1e-4f), 1e-6f, 1e6f);
        c11[j] = clipf(fmaf(ssy, ssy, 1e-4f), 1e-6f, 1e6f);
    }

    // proj_points: float4 [0, 3G)
    __stcs(&out4[3 * g + 0], make_float4(xs[0], ys[0], zs[0], xs[1]));
    __stcs(&out4[3 * g + 1], make_float4(ys[1], zs[1], xs[2], ys[2]));
    __stcs(&out4[3 * g + 2], make_float4(zs[2], xs[3], ys[3], zs[3]));

    // cov2d: float4 [3G, 7G), one per gaussian
    long cb = 3L * G;
#pragma unroll
    for (int j = 0; j < 4; j++)
        __stcs(&out4[cb + 4L * g + j], make_float4(c00[j], 1e-6f, 1e-6f, c11[j]));

    // valid: float4 [11G, 12G)
    __stcs(&out4[11L * G + g], make_float4(vf[0], vf[1], vf[2], vf[3]));
}

// ---------------------------------------------------------------------------
// Kernel B: elementwise colors clip + opacity sigmoid.
// thread i < 3G: colors float4;  i >= 3G: opacity float4.
// ---------------------------------------------------------------------------
__global__ void __launch_bounds__(256)
gs_elem_kernel(const float4* __restrict__ col4,
               const float4* __restrict__ op4,
               float4* __restrict__ out4, int G)
{
    int i = blockIdx.x * blockDim.x + threadIdx.x;
    int CG = 3 * G;
    if (i < CG) {
        float4 c = __ldcs(&col4[i]);
        c.x = clipf(c.x, 0.0f, 1.0f);
        c.y = clipf(c.y, 0.0f, 1.0f);
        c.z = clipf(c.z, 0.0f, 1.0f);
        c.w = clipf(c.w, 0.0f, 1.0f);
        __stcs(&out4[7L * G + i], c);
    } else if (i < 4 * G) {
        int j = i - CG;
        float4 o = __ldcs(&op4[j]);
        o.x = __fdividef(1.0f, 1.0f + __expf(-o.x));
        o.y = __fdividef(1.0f, 1.0f + __expf(-o.y));
        o.z = __fdividef(1.0f, 1.0f + __expf(-o.z));
        o.w = __fdividef(1.0f, 1.0f + __expf(-o.w));
        __stcs(&out4[10L * G + j], o);
    }
}

// ---------------------------------------------------------------------------
// Scalar fallback for N % 4 != 0 (not expected with N = 4,000,000).
// ---------------------------------------------------------------------------
__global__ void __launch_bounds__(256)
gs_scalar_kernel(const float* __restrict__ pos,
                 const float* __restrict__ sc,
                 const float* __restrict__ col,
                 const float* __restrict__ op,
                 const float* __restrict__ vm,
                 const int*   __restrict__ wp,
                 const int*   __restrict__ hp,
                 float* __restrict__ out, int N)
{
    int i = blockIdx.x * blockDim.x + threadIdx.x;
    if (i >= N) return;

    float r00 = vm[0], r01 = vm[1],  r02 = vm[2],  tx = vm[3];
    float r10 = vm[4], r11 = vm[5],  r12 = vm[6],  ty = vm[7];
    float r20 = vm[8], r21 = vm[9],  r22 = vm[10], tz = vm[11];
    float W = (float)(*wp), H = (float)(*hp);
    float hw = W * 0.5f, hh = H * 0.5f;
    float xmax = W + 1000.0f, ymax = H + 1000.0f;

    float ax = pos[3*i] - tx, ay = pos[3*i+1] - ty, az = pos[3*i+2] - tz;
    float vx = clipf(fmaf(r00, ax, fmaf(r01, ay, r02 * az)), -100.0f, 100.0f);
    float vy = clipf(fmaf(r10, ax, fmaf(r11, ay, r12 * az)), -100.0f, 100.0f);
    float vz = clipf(fmaf(r20, ax, fmaf(r21, ay, r22 * az)), -100.0f, 100.0f);

    float z   = clipf(vz, 0.1f, 10.0f);
    float inv = __fdividef(GS_FX, z);

    long n = N;
    out[3*i+0] = clipf(fmaf(vx, inv, hw), -1000.0f, xmax);
    out[3*i+1] = clipf(fmaf(-vy, inv, hh), -1000.0f, ymax);
    out[3*i+2] = vz;

    float ssx = fmaxf(sc[3*i],   0.001f) * inv;
    float ssy = fmaxf(sc[3*i+1], 0.001f) * inv;
    out[3*n + 4L*i + 0] = clipf(fmaf(ssx, ssx, 1e-4f), 1e-6f, 1e6f);
    out[3*n + 4L*i + 1] = 1e-6f;
    out[3*n + 4L*i + 2] = 1e-6f;
    out[3*n + 4L*i + 3] = clipf(fmaf(ssy, ssy, 1e-4f), 1e-6f, 1e6f);

    out[7*n + 3L*i + 0] = clipf(col[3*i+0], 0.f, 1.f);
    out[7*n + 3L*i + 1] = clipf(col[3*i+1], 0.f, 1.f);
    out[7*n + 3L*i + 2] = clipf(col[3*i+2], 0.f, 1.f);

    out[10*n + i] = __fdividef(1.0f, 1.0f + __expf(-op[i]));
    out[11*n + i] = (vz > 0.1f && vz < 10.0f) ? 1.0f : 0.0f;
}

extern "C" void kernel_launch(void* const* d_in, const int* in_sizes, int n_in,
                              void* d_out, int out_size)
{
    const float* positions = (const float*)d_in[0];
    const float* scales    = (const float*)d_in[1];
    // d_in[2] rotations: unused by the reference math
    const float* colors    = (const float*)d_in[3];
    const float* opac      = (const float*)d_in[4];
    const float* viewmat   = (const float*)d_in[5];
    // d_in[6] projmat: unused
    const int*   wp        = (const int*)d_in[7];
    const int*   hp        = (const int*)d_in[8];
    float* out = (float*)d_out;

    int N = in_sizes[0] / 3;

    if ((N & 3) == 0) {
        int G = N >> 2;
        int threads = 256;
        int geo_blocks  = (G + threads - 1) / threads;
        int elem_blocks = (4 * G + threads - 1) / threads;
        gs_geo_kernel<<<geo_blocks, threads>>>(
            (const float4*)positions, (const float4*)scales,
            viewmat, wp, hp, (float4*)out, G);
        gs_elem_kernel<<<elem_blocks, threads>>>(
            (const float4*)colors, (const float4*)opac, (float4*)out, G);
    } else {
        int threads = 256;
        int blocks = (N + threads - 1) / threads;
        gs_scalar_kernel<<<blocks, threads>>>(
            positions, scales, colors, opac, viewmat, wp, hp, out, N);
    }
}